// round 10
// baseline (speedup 1.0000x reference)
#include <cuda_runtime.h>
#include <math_constants.h>
#include <cstdint>

// ---------------- problem constants ----------------
#define BATCHSZ 4096
#define DIM     256
#define NROWS   8192
#define NCH     4               // column chunks (2048 cols each)
#define TPC     16              // tiles per CTA (2048 / 128)
#define NKC     8               // 32-K chunks per tile
#define NCHUNKT (TPC * NKC)     // 128 chunks per CTA
// prescale = sqrt(2 * log2(e)): product of two prescaled values = sim * 2 * log2e
#define PRESCALE 1.6986436f
#define LN2F     0.69314718055994531f

// ---------------- device scratch (no allocs allowed) ----------------
__device__ uint32_t g_afrag[64 * 16384];        // [rt][t16][ks][lane][4reg] 4MB
__device__ uint32_t g_bfrag[64 * 8 * 2048];     // [ct][kc][nt][ks][lane][2reg] 4MB
__device__ float g_pm[NCH][NROWS];
__device__ float g_ps[NCH][NROWS];
__device__ float g_lrow[NROWS];

// ---------------- smem layout (u32 words) ----------------
#define A_U32    16384                  // A tile fragments (64KB)
#define B_OFF    16384                  // 3 chunk buffers x 2048 u32 (8KB each)
#define B_BUF    2048
#define RED_OFF  (B_OFF + 3 * B_BUF)    // 22528: [4 wn][128 rows][m,s] floats
#define SMEM_U32 (RED_OFF + 1024)       // 23552
#define SMEM_BYTES (SMEM_U32 * 4)       // 94208

// ---------------- helpers ----------------
static __device__ __forceinline__ uint32_t f2bf2(float lo, float hi) {
    uint32_t r;   // d = {hi, lo}
    asm("cvt.rn.bf16x2.f32 %0, %1, %2;" : "=r"(r) : "f"(hi), "f"(lo));
    return r;
}
static __device__ __forceinline__ float ex2f(float x) {
    float y;
    asm("ex2.approx.ftz.f32 %0, %1;" : "=f"(y) : "f"(x));
    return y;
}
static __device__ __forceinline__ uint32_t smem_u32(const void* p) {
    uint32_t a;
    asm("{ .reg .u64 t; cvta.to.shared.u64 t, %1; cvt.u32.u64 %0, t; }" : "=r"(a) : "l"(p));
    return a;
}
static __device__ __forceinline__ void mma_bf16(float c[4],
        uint32_t a0, uint32_t a1, uint32_t a2, uint32_t a3,
        uint32_t b0, uint32_t b1) {
    asm volatile(
        "mma.sync.aligned.m16n8k16.row.col.f32.bf16.bf16.f32 "
        "{%0,%1,%2,%3}, {%4,%5,%6,%7}, {%8,%9}, {%0,%1,%2,%3};"
        : "+f"(c[0]), "+f"(c[1]), "+f"(c[2]), "+f"(c[3])
        : "r"(a0), "r"(a1), "r"(a2), "r"(a3), "r"(b0), "r"(b1));
}
#define CP_ASYNC16(dst, src) \
    asm volatile("cp.async.cg.shared.global [%0], [%1], 16;" :: "r"(dst), "l"(src))
#define CP_COMMIT() asm volatile("cp.async.commit_group;" ::: "memory")
#define CP_WAIT(n)  asm volatile("cp.async.wait_group %0;" :: "n"(n) : "memory")

static __device__ __forceinline__ const float* srow(const float* hi, const float* hj, int r) {
    return (r < BATCHSZ) ? (hi + (size_t)r * DIM) : (hj + (size_t)(r - BATCHSZ) * DIM);
}

// ==========================================================================
// Pre-pass: convert inputs to pre-scaled bf16 fragment-major layouts.
// Blocks [0,1024): g_afrag. Blocks [1024,2048): g_bfrag. 4 u32 per thread.
// ==========================================================================
__global__ void prep_kernel(const float* __restrict__ hi, const float* __restrict__ hj) {
    const int tid = threadIdx.x;
    if (blockIdx.x < 1024) {
        // afrag: ai = rt<<14 | t16<<11 | ks<<7 | lane<<2 | reg
        const int ai = blockIdx.x * 1024 + tid * 4;
        const int rt = ai >> 14, rem = ai & 16383;
        const int t16 = rem >> 11, ks = (rem >> 7) & 15, l = (rem >> 2) & 31;
        const int g = l >> 2, tq = l & 3;
        const int row0 = rt * 128 + t16 * 16 + g;
        const int kb = ks * 16 + tq * 2;
#pragma unroll
        for (int reg = 0; reg < 4; reg++) {
            const int row = row0 + (reg & 1) * 8;
            const int k = kb + (reg >> 1) * 8;
            const float2 v = *(const float2*)(srow(hi, hj, row) + k);
            g_afrag[ai + reg] = f2bf2(v.x * PRESCALE, v.y * PRESCALE);
        }
    } else {
        // bfrag: bi = ct<<14 | kc<<11 | nt<<7 | ks<<6 | lane<<1 | reg
        const int b0 = (blockIdx.x - 1024) * 1024 + tid * 4;
#pragma unroll
        for (int j = 0; j < 4; j++) {
            const int bi = b0 + j;
            const int ct = bi >> 14, rem = bi & 16383;
            const int kc = rem >> 11, nt = (rem >> 7) & 15;
            const int ks = (rem >> 6) & 1, l = (rem >> 1) & 31, reg = bi & 1;
            const int col = ct * 128 + nt * 8 + (l >> 2);
            const int k = kc * 32 + ks * 16 + (l & 3) * 2 + reg * 8;
            const float2 v = *(const float2*)(srow(hi, hj, col) + k);
            g_bfrag[bi] = f2bf2(v.x * PRESCALE, v.y * PRESCALE);
        }
    }
}

// ==========================================================================
// Fused bf16 mma.sync GEMM + online logsumexp (base-2), cp.async pipeline.
// CTA = (row tile rt: 128 rows, A resident) x (column chunk ch: 2048 cols).
// 8 warps, warp grid 2m x 4n, warp tile 64x32, m16n8k16 bf16 (f32 accum).
// Epilogue is fully register-resident: each warp keeps 8 running (m, s)
// segments across all 16 tiles; single cross-warp smem merge at the end.
// ==========================================================================
__global__ __launch_bounds__(256, 2)
void ntxent_mma_kernel() {
    extern __shared__ float smf[];
    uint32_t* smu = (uint32_t*)smf;
    const uint32_t sbase = smem_u32(smf);
    const int tid = threadIdx.x;
    const int w = tid >> 5, lane = tid & 31;
    const int g = lane >> 2, tq = lane & 3;
    const int wm = w >> 2, wn = w & 3;          // warp grid 2 x 4

    const int rt = blockIdx.x & 63;
    const int ch = blockIdx.x >> 6;
    const int r0 = rt * 128;
    // The self-similarity diagonal lives in exactly one tile of one chunk:
    const int tdiag = ((rt >> 4) == ch) ? (rt & 15) : -1;

    const uint32_t* asrc = g_afrag + (size_t)rt * 16384;
    const uint32_t* bbase = g_bfrag + (size_t)ch * 128 * 2048;

    // -------- prologue: cp.async A tile (group 0), chunks 0 & 1 --------
#pragma unroll
    for (int i = 0; i < 16; i++) {
        const int ga = i * 256 + tid;
        CP_ASYNC16(sbase + ga * 16, asrc + ga * 4);
    }
    CP_COMMIT();
#pragma unroll
    for (int c = 0; c < 2; c++) {
#pragma unroll
        for (int i = 0; i < 2; i++) {
            const int gi = i * 256 + tid;
            CP_ASYNC16(sbase + (B_OFF + c * B_BUF + gi * 4) * 4,
                       bbase + (size_t)c * 2048 + gi * 4);
        }
        CP_COMMIT();
    }

    float acc[4][4][4];
#pragma unroll
    for (int mf = 0; mf < 4; mf++)
#pragma unroll
        for (int nf = 0; nf < 4; nf++)
#pragma unroll
            for (int c = 0; c < 4; c++) acc[mf][nf][c] = 0.f;

    // Running per-segment (m, s): seg s = mf*2+hh covers row wm*64+mf*16+g+hh*8.
    float rM[8], rS[8];
#pragma unroll
    for (int s = 0; s < 8; s++) { rM[s] = -CUDART_INF_F; rS[s] = 0.f; }

    int cbuf = 0;                                // buffer of current chunk
    int gc = 0;                                  // global chunk index 0..127

    for (int t = 0; t < TPC; t++) {
        for (int kc = 0; kc < NKC; kc++) {
            // wait until chunk gc is resident (groups complete in order)
            if (gc < NCHUNKT - 2)       CP_WAIT(2);
            else if (gc == NCHUNKT - 2) CP_WAIT(1);
            else                        CP_WAIT(0);
            __syncthreads();            // all warps done with the reused buffer

            if (gc + 2 < NCHUNKT) {     // refill that buffer with chunk gc+2
                const int ib = (cbuf + 2 >= 3) ? cbuf - 1 : cbuf + 2;
                const uint32_t* src = bbase + (size_t)(gc + 2) * 2048;
#pragma unroll
                for (int i = 0; i < 2; i++) {
                    const int gi = i * 256 + tid;
                    CP_ASYNC16(sbase + (B_OFF + ib * B_BUF + gi * 4) * 4, src + gi * 4);
                }
                CP_COMMIT();
            }

            // -------- MMA: 2 k16-steps on chunk gc --------
            const uint32_t* Bu = smu + B_OFF + cbuf * B_BUF;
#pragma unroll
            for (int ksl = 0; ksl < 2; ksl++) {
                uint2 bfr[4];
#pragma unroll
                for (int nf = 0; nf < 4; nf++)
                    bfr[nf] = *(const uint2*)(Bu + ((wn * 4 + nf) * 2 + ksl) * 64
                                              + lane * 2);
#pragma unroll
                for (int mf = 0; mf < 4; mf++) {
                    const uint4 af = *(const uint4*)(smu
                        + ((wm * 4 + mf) * 16 + (kc * 2 + ksl)) * 128 + lane * 4);
#pragma unroll
                    for (int nf = 0; nf < 4; nf++)
                        mma_bf16(acc[mf][nf], af.x, af.y, af.z, af.w,
                                 bfr[nf].x, bfr[nf].y);
                }
            }
            cbuf = (cbuf == 2) ? 0 : cbuf + 1;
            gc++;
        }

        // -------- epilogue: fold tile into register-resident (m, s), base-2 ----
        {
            const bool hd = (t == tdiag);
            // TILE-LOCAL column base (bugfix vs R9: no t*128 term here —
            // both sides of the diagonal compare are tile-local in [0,128)).
            const int cloc = wn * 32 + tq * 2;
            const int rloc = wm * 64 + g;                // tile-local row base
#pragma unroll
            for (int mf = 0; mf < 4; mf++)
#pragma unroll
                for (int hh = 0; hh < 2; hh++) {
                    const int s = mf * 2 + hh;
                    float m = -CUDART_INF_F;
                    if (hd) {
                        const int gr = rloc + mf * 16 + hh * 8;  // tile-local row
#pragma unroll
                        for (int nf = 0; nf < 4; nf++)
#pragma unroll
                            for (int c = 0; c < 2; c++) {
                                float v = acc[mf][nf][hh * 2 + c];
                                if (gr == cloc + nf * 8 + c) v = -CUDART_INF_F;
                                acc[mf][nf][hh * 2 + c] = v;
                                m = fmaxf(m, v);
                            }
                    } else {
#pragma unroll
                        for (int nf = 0; nf < 4; nf++)
#pragma unroll
                            for (int c = 0; c < 2; c++)
                                m = fmaxf(m, acc[mf][nf][hh * 2 + c]);
                    }
                    m = fmaxf(m, __shfl_xor_sync(0xffffffffu, m, 1));
                    m = fmaxf(m, __shfl_xor_sync(0xffffffffu, m, 2));
                    float sv = 0.f;
#pragma unroll
                    for (int nf = 0; nf < 4; nf++)
#pragma unroll
                        for (int c = 0; c < 2; c++)
                            sv += ex2f(acc[mf][nf][hh * 2 + c] - m);
                    sv += __shfl_xor_sync(0xffffffffu, sv, 1);
                    sv += __shfl_xor_sync(0xffffffffu, sv, 2);
                    const float nm = fmaxf(rM[s], m);
                    rS[s] = rS[s] * ex2f(rM[s] - nm) + sv * ex2f(m - nm);
                    rM[s] = nm;
#pragma unroll
                    for (int nf = 0; nf < 4; nf++)
#pragma unroll
                        for (int c = 0; c < 2; c++)
                            acc[mf][nf][hh * 2 + c] = 0.f;
                }
        }
    }

    // -------- final cross-warp merge (once) --------
    {
        float* red = smf + RED_OFF;              // [wn][128 rows][m,s]
        if (tq == 0) {
#pragma unroll
            for (int s = 0; s < 8; s++) {
                const int row = wm * 64 + (s >> 1) * 16 + g + (s & 1) * 8;
                red[(wn * 128 + row) * 2 + 0] = rM[s];
                red[(wn * 128 + row) * 2 + 1] = rS[s];
            }
        }
        __syncthreads();
        if (tid < 128) {                         // thread tid owns row r0+tid
            float M = red[tid * 2];
#pragma unroll
            for (int q = 1; q < 4; q++) M = fmaxf(M, red[(q * 128 + tid) * 2]);
            float S = 0.f;
#pragma unroll
            for (int q = 0; q < 4; q++)
                S += red[(q * 128 + tid) * 2 + 1] * ex2f(red[(q * 128 + tid) * 2] - M);
            g_pm[ch][r0 + tid] = M;              // base-2 max of sim*2*log2e
            g_ps[ch][r0 + tid] = S;              // base-2 sumexp
        }
    }
}

// ==========================================================================
// Merge 4 column-chunk partials per row (base-2), exact fp32 pos, per-row loss.
// ==========================================================================
__global__ void combine_kernel(const float* __restrict__ hi, const float* __restrict__ hj) {
    const int gwarp = (int)((blockIdx.x * blockDim.x + threadIdx.x) >> 5);
    const int lane = threadIdx.x & 31;
    if (gwarp >= BATCHSZ) return;

    const float* a = hi + (size_t)gwarp * DIM;
    const float* b = hj + (size_t)gwarp * DIM;
    const int k = lane * 8;
    float4 a0 = *(const float4*)(a + k);
    float4 a1 = *(const float4*)(a + k + 4);
    float4 b0 = *(const float4*)(b + k);
    float4 b1 = *(const float4*)(b + k + 4);
    float d = a0.x * b0.x + a0.y * b0.y + a0.z * b0.z + a0.w * b0.w
            + a1.x * b1.x + a1.y * b1.y + a1.z * b1.z + a1.w * b1.w;
#pragma unroll
    for (int off = 16; off > 0; off >>= 1)
        d += __shfl_xor_sync(0xffffffffu, d, off);
    const float pos = d * 2.0f;                  // exact fp32 sim / temp

    if (lane < 2) {
        const int r = gwarp + lane * BATCHSZ;
        float M = g_pm[0][r];
#pragma unroll
        for (int c = 1; c < NCH; c++) M = fmaxf(M, g_pm[c][r]);
        float S = 0.f;
#pragma unroll
        for (int c = 0; c < NCH; c++) S += g_ps[c][r] * ex2f(g_pm[c][r] - M);
        g_lrow[r] = LN2F * (M + __log2f(S)) - pos;   // lse_e - pos
    }
}

// Deterministic single-block reduction -> mean (replay-stable, no atomics).
__global__ void reduce_kernel(float* __restrict__ out) {
    __shared__ float sm[256];
    const int tid = threadIdx.x;
    float s = 0.f;
    for (int i = tid; i < NROWS; i += 256) s += g_lrow[i];
    sm[tid] = s;
    __syncthreads();
    for (int stride = 128; stride > 0; stride >>= 1) {
        if (tid < stride) sm[tid] += sm[tid + stride];
        __syncthreads();
    }
    if (tid == 0) out[0] = sm[0] * (1.0f / NROWS);
}

extern "C" void kernel_launch(void* const* d_in, const int* in_sizes, int n_in,
                              void* d_out, int out_size) {
    const float* hi = (const float*)d_in[0];
    const float* hj = (const float*)d_in[1];
    float* out = (float*)d_out;

    prep_kernel<<<2048, 256>>>(hi, hj);
    cudaFuncSetAttribute(ntxent_mma_kernel,
                         cudaFuncAttributeMaxDynamicSharedMemorySize, SMEM_BYTES);
    ntxent_mma_kernel<<<64 * NCH, 256, SMEM_BYTES>>>();
    combine_kernel<<<(BATCHSZ * 32) / 256, 256>>>(hi, hj);
    reduce_kernel<<<1, 256>>>(out);
}

// round 15
// speedup vs baseline: 1.0876x; 1.0876x over previous
#include <cuda_runtime.h>
#include <math_constants.h>
#include <cstdint>

// ---------------- problem constants ----------------
#define BATCHSZ 4096
#define DIM     256
#define NROWS   8192
#define NCH     16              // column chunks (512 cols each)
#define TPC     4               // 128-col tiles per item (512 / 128)
#define NKC     8               // 32-K chunks per tile
#define NCHUNKT (TPC * NKC)     // 32 chunks per item
// prescale = sqrt(2 * log2(e)): product of two prescaled values = sim * 2 * log2e
#define PRESCALE 1.6986436f
#define LN2F     0.69314718055994531f

// ---------------- device scratch (no allocs allowed) ----------------
__device__ uint32_t g_afrag[64 * 16384];        // [rt][t16][ks][lane][4reg] 4MB
__device__ uint32_t g_bfrag[64 * 8 * 2048];     // [tile128][kc][nt][ks][lane][2reg] 4MB
__device__ float g_pm[NCH][NROWS];
__device__ float g_ps[NCH][NROWS];
__device__ float g_lrow[NROWS];

// ---------------- smem layout (u32 words) ----------------
#define A_U32    16384                  // A tile fragments (64KB)
#define B_OFF    16384                  // 3 chunk buffers x 2048 u32 (8KB each)
#define B_BUF    2048
#define RED_OFF  (B_OFF + 3 * B_BUF)    // 22528: [4 wn][128 rows][m,s] floats
#define SMEM_U32 (RED_OFF + 1024)       // 23552
#define SMEM_BYTES (SMEM_U32 * 4)       // 94208

// ---------------- helpers ----------------
static __device__ __forceinline__ uint32_t f2bf2(float lo, float hi) {
    uint32_t r;   // d = {hi, lo}
    asm("cvt.rn.bf16x2.f32 %0, %1, %2;" : "=r"(r) : "f"(hi), "f"(lo));
    return r;
}
static __device__ __forceinline__ float ex2f(float x) {
    float y;
    asm("ex2.approx.ftz.f32 %0, %1;" : "=f"(y) : "f"(x));
    return y;
}
static __device__ __forceinline__ uint32_t smem_u32(const void* p) {
    uint32_t a;
    asm("{ .reg .u64 t; cvta.to.shared.u64 t, %1; cvt.u32.u64 %0, t; }" : "=r"(a) : "l"(p));
    return a;
}
static __device__ __forceinline__ void mma_bf16(float c[4],
        uint32_t a0, uint32_t a1, uint32_t a2, uint32_t a3,
        uint32_t b0, uint32_t b1) {
    asm volatile(
        "mma.sync.aligned.m16n8k16.row.col.f32.bf16.bf16.f32 "
        "{%0,%1,%2,%3}, {%4,%5,%6,%7}, {%8,%9}, {%0,%1,%2,%3};"
        : "+f"(c[0]), "+f"(c[1]), "+f"(c[2]), "+f"(c[3])
        : "r"(a0), "r"(a1), "r"(a2), "r"(a3), "r"(b0), "r"(b1));
}
#define CP_ASYNC16(dst, src) \
    asm volatile("cp.async.cg.shared.global [%0], [%1], 16;" :: "r"(dst), "l"(src))
#define CP_COMMIT() asm volatile("cp.async.commit_group;" ::: "memory")
#define CP_WAIT(n)  asm volatile("cp.async.wait_group %0;" :: "n"(n) : "memory")

static __device__ __forceinline__ const float* srow(const float* hi, const float* hj, int r) {
    return (r < BATCHSZ) ? (hi + (size_t)r * DIM) : (hj + (size_t)(r - BATCHSZ) * DIM);
}

// ==========================================================================
// Pre-pass: convert inputs to pre-scaled bf16 fragment-major layouts.
// Blocks [0,1024): g_afrag. Blocks [1024,2048): g_bfrag. 4 u32 per thread.
// ==========================================================================
__global__ void prep_kernel(const float* __restrict__ hi, const float* __restrict__ hj) {
    const int tid = threadIdx.x;
    if (blockIdx.x < 1024) {
        // afrag: ai = rt<<14 | t16<<11 | ks<<7 | lane<<2 | reg
        const int ai = blockIdx.x * 1024 + tid * 4;
        const int rt = ai >> 14, rem = ai & 16383;
        const int t16 = rem >> 11, ks = (rem >> 7) & 15, l = (rem >> 2) & 31;
        const int g = l >> 2, tq = l & 3;
        const int row0 = rt * 128 + t16 * 16 + g;
        const int kb = ks * 16 + tq * 2;
#pragma unroll
        for (int reg = 0; reg < 4; reg++) {
            const int row = row0 + (reg & 1) * 8;
            const int k = kb + (reg >> 1) * 8;
            const float2 v = *(const float2*)(srow(hi, hj, row) + k);
            g_afrag[ai + reg] = f2bf2(v.x * PRESCALE, v.y * PRESCALE);
        }
    } else {
        // bfrag: bi = tile128<<14 | kc<<11 | nt<<7 | ks<<6 | lane<<1 | reg
        const int b0 = (blockIdx.x - 1024) * 1024 + tid * 4;
#pragma unroll
        for (int j = 0; j < 4; j++) {
            const int bi = b0 + j;
            const int ct = bi >> 14, rem = bi & 16383;
            const int kc = rem >> 11, nt = (rem >> 7) & 15;
            const int ks = (rem >> 6) & 1, l = (rem >> 1) & 31, reg = bi & 1;
            const int col = ct * 128 + nt * 8 + (l >> 2);
            const int k = kc * 32 + ks * 16 + (l & 3) * 2 + reg * 8;
            const float2 v = *(const float2*)(srow(hi, hj, col) + k);
            g_bfrag[bi] = f2bf2(v.x * PRESCALE, v.y * PRESCALE);
        }
    }
}

// ==========================================================================
// Fused bf16 mma.sync GEMM + online logsumexp (base-2), cp.async pipeline.
// Work item (CTA) = (row tile rt: 128 rows, A resident) x (512-col chunk ct).
// 1024 fine-grained items over ~296 resident slots -> HW work-stealing evens
// the tensor load across all 148 SMs. 8 warps, warp grid 2m x 4n, warp tile
// 64x32, m16n8k16 bf16 (f32 accum); register-resident per-warp online LSE.
// Pipeline (race-fixed): wait_group(1) BEFORE consuming chunk gc guarantees
// its in-order cp.async group completed; the gc+2 prefetch is committed
// after the wait, keeping 2 copies in flight under the MMA.
// ==========================================================================
__global__ __launch_bounds__(256, 2)
void ntxent_mma_kernel() {
    extern __shared__ float smf[];
    uint32_t* smu = (uint32_t*)smf;
    const uint32_t sbase = smem_u32(smf);
    const int tid = threadIdx.x;
    const int w = tid >> 5, lane = tid & 31;
    const int g = lane >> 2, tq = lane & 3;
    const int wm = w >> 2, wn = w & 3;          // warp grid 2 x 4

    const int rt = blockIdx.x & 63;
    const int ct = blockIdx.x >> 6;             // 512-col chunk 0..15
    const int r0 = rt * 128;
    // Diagonal 128-col tile lives in this item iff ct == rt>>2; local index rt&3.
    const int tdiag = (ct == (rt >> 2)) ? (rt & 3) : -1;

    const uint32_t* asrc = g_afrag + (size_t)rt * 16384;
    const uint32_t* bbase = g_bfrag + (size_t)ct * NCHUNKT * 2048;

    // -------- prologue: cp.async A tile (group 0), chunks 0 & 1 --------
#pragma unroll
    for (int i = 0; i < 16; i++) {
        const int ga = i * 256 + tid;
        CP_ASYNC16(sbase + ga * 16, asrc + ga * 4);
    }
    CP_COMMIT();
#pragma unroll
    for (int c = 0; c < 2; c++) {
#pragma unroll
        for (int i = 0; i < 2; i++) {
            const int gi = i * 256 + tid;
            CP_ASYNC16(sbase + (B_OFF + c * B_BUF + gi * 4) * 4,
                       bbase + (size_t)c * 2048 + gi * 4);
        }
        CP_COMMIT();
    }

    float acc[4][4][4];
#pragma unroll
    for (int mf = 0; mf < 4; mf++)
#pragma unroll
        for (int nf = 0; nf < 4; nf++)
#pragma unroll
            for (int c = 0; c < 4; c++) acc[mf][nf][c] = 0.f;

    // Running per-segment (m, s): seg s = mf*2+hh covers row wm*64+mf*16+g+hh*8.
    float rM[8], rS[8];
#pragma unroll
    for (int s = 0; s < 8; s++) { rM[s] = -CUDART_INF_F; rS[s] = 0.f; }

    int cbuf = 0;                                // buffer of current chunk
    int gc = 0;                                  // chunk index 0..31

    for (int t = 0; t < TPC; t++) {
        for (int kc = 0; kc < NKC; kc++) {
            // Guarantee chunk gc's group completed: groups finish in order, so
            // allowing only 1 outstanding (the gc+1 prefetch) retires c_gc.
            if (gc < NCHUNKT - 1) CP_WAIT(1);
            else                  CP_WAIT(0);
            __syncthreads();            // all warps done with the reused buffer

            if (gc + 2 < NCHUNKT) {     // refill that buffer with chunk gc+2
                const int ib = (cbuf + 2 >= 3) ? cbuf - 1 : cbuf + 2;
                const uint32_t* src = bbase + (size_t)(gc + 2) * 2048;
#pragma unroll
                for (int i = 0; i < 2; i++) {
                    const int gi = i * 256 + tid;
                    CP_ASYNC16(sbase + (B_OFF + ib * B_BUF + gi * 4) * 4, src + gi * 4);
                }
                CP_COMMIT();
            }

            // -------- MMA: 2 k16-steps on chunk gc --------
            const uint32_t* Bu = smu + B_OFF + cbuf * B_BUF;
#pragma unroll
            for (int ksl = 0; ksl < 2; ksl++) {
                uint2 bfr[4];
#pragma unroll
                for (int nf = 0; nf < 4; nf++)
                    bfr[nf] = *(const uint2*)(Bu + ((wn * 4 + nf) * 2 + ksl) * 64
                                              + lane * 2);
#pragma unroll
                for (int mf = 0; mf < 4; mf++) {
                    const uint4 af = *(const uint4*)(smu
                        + ((wm * 4 + mf) * 16 + (kc * 2 + ksl)) * 128 + lane * 4);
#pragma unroll
                    for (int nf = 0; nf < 4; nf++)
                        mma_bf16(acc[mf][nf], af.x, af.y, af.z, af.w,
                                 bfr[nf].x, bfr[nf].y);
                }
            }
            cbuf = (cbuf == 2) ? 0 : cbuf + 1;
            gc++;
        }

        // -------- epilogue: fold tile into register-resident (m, s), base-2 ----
        {
            const bool hd = (t == tdiag);
            const int cloc = wn * 32 + tq * 2;           // tile-local col base
            const int rloc = wm * 64 + g;                // tile-local row base
#pragma unroll
            for (int mf = 0; mf < 4; mf++)
#pragma unroll
                for (int hh = 0; hh < 2; hh++) {
                    const int s = mf * 2 + hh;
                    float m = -CUDART_INF_F;
                    if (hd) {
                        const int gr = rloc + mf * 16 + hh * 8;  // tile-local row
#pragma unroll
                        for (int nf = 0; nf < 4; nf++)
#pragma unroll
                            for (int c = 0; c < 2; c++) {
                                float v = acc[mf][nf][hh * 2 + c];
                                if (gr == cloc + nf * 8 + c) v = -CUDART_INF_F;
                                acc[mf][nf][hh * 2 + c] = v;
                                m = fmaxf(m, v);
                            }
                    } else {
#pragma unroll
                        for (int nf = 0; nf < 4; nf++)
#pragma unroll
                            for (int c = 0; c < 2; c++)
                                m = fmaxf(m, acc[mf][nf][hh * 2 + c]);
                    }
                    m = fmaxf(m, __shfl_xor_sync(0xffffffffu, m, 1));
                    m = fmaxf(m, __shfl_xor_sync(0xffffffffu, m, 2));
                    float sv = 0.f;
#pragma unroll
                    for (int nf = 0; nf < 4; nf++)
#pragma unroll
                        for (int c = 0; c < 2; c++)
                            sv += ex2f(acc[mf][nf][hh * 2 + c] - m);
                    sv += __shfl_xor_sync(0xffffffffu, sv, 1);
                    sv += __shfl_xor_sync(0xffffffffu, sv, 2);
                    const float nm = fmaxf(rM[s], m);
                    rS[s] = rS[s] * ex2f(rM[s] - nm) + sv * ex2f(m - nm);
                    rM[s] = nm;
#pragma unroll
                    for (int nf = 0; nf < 4; nf++)
#pragma unroll
                        for (int c = 0; c < 2; c++)
                            acc[mf][nf][hh * 2 + c] = 0.f;
                }
        }
    }

    // -------- final cross-warp merge (once per item) --------
    {
        float* red = smf + RED_OFF;              // [wn][128 rows][m,s]
        if (tq == 0) {
#pragma unroll
            for (int s = 0; s < 8; s++) {
                const int row = wm * 64 + (s >> 1) * 16 + g + (s & 1) * 8;
                red[(wn * 128 + row) * 2 + 0] = rM[s];
                red[(wn * 128 + row) * 2 + 1] = rS[s];
            }
        }
        __syncthreads();
        if (tid < 128) {                         // thread tid owns row r0+tid
            float M = red[tid * 2];
#pragma unroll
            for (int q = 1; q < 4; q++) M = fmaxf(M, red[(q * 128 + tid) * 2]);
            float S = 0.f;
#pragma unroll
            for (int q = 0; q < 4; q++)
                S += red[(q * 128 + tid) * 2 + 1] * ex2f(red[(q * 128 + tid) * 2] - M);
            g_pm[ct][r0 + tid] = M;              // base-2 max of sim*2*log2e
            g_ps[ct][r0 + tid] = S;              // base-2 sumexp
        }
    }
}

// ==========================================================================
// Merge 16 column-chunk partials per row (base-2), exact fp32 pos, per-row loss.
// ==========================================================================
__global__ void combine_kernel(const float* __restrict__ hi, const float* __restrict__ hj) {
    const int gwarp = (int)((blockIdx.x * blockDim.x + threadIdx.x) >> 5);
    const int lane = threadIdx.x & 31;
    if (gwarp >= BATCHSZ) return;

    const float* a = hi + (size_t)gwarp * DIM;
    const float* b = hj + (size_t)gwarp * DIM;
    const int k = lane * 8;
    float4 a0 = *(const float4*)(a + k);
    float4 a1 = *(const float4*)(a + k + 4);
    float4 b0 = *(const float4*)(b + k);
    float4 b1 = *(const float4*)(b + k + 4);
    float d = a0.x * b0.x + a0.y * b0.y + a0.z * b0.z + a0.w * b0.w
            + a1.x * b1.x + a1.y * b1.y + a1.z * b1.z + a1.w * b1.w;
#pragma unroll
    for (int off = 16; off > 0; off >>= 1)
        d += __shfl_xor_sync(0xffffffffu, d, off);
    const float pos = d * 2.0f;                  // exact fp32 sim / temp

    if (lane < 2) {
        const int r = gwarp + lane * BATCHSZ;
        float M = g_pm[0][r];
#pragma unroll
        for (int c = 1; c < NCH; c++) M = fmaxf(M, g_pm[c][r]);
        float S = 0.f;
#pragma unroll
        for (int c = 0; c < NCH; c++) S += g_ps[c][r] * ex2f(g_pm[c][r] - M);
        g_lrow[r] = LN2F * (M + __log2f(S)) - pos;   // lse_e - pos
    }
}

// Deterministic single-block reduction -> mean (replay-stable, no atomics).
__global__ void reduce_kernel(float* __restrict__ out) {
    __shared__ float sm[256];
    const int tid = threadIdx.x;
    float s = 0.f;
    for (int i = tid; i < NROWS; i += 256) s += g_lrow[i];
    sm[tid] = s;
    __syncthreads();
    for (int stride = 128; stride > 0; stride >>= 1) {
        if (tid < stride) sm[tid] += sm[tid + stride];
        __syncthreads();
    }
    if (tid == 0) out[0] = sm[0] * (1.0f / NROWS);
}

extern "C" void kernel_launch(void* const* d_in, const int* in_sizes, int n_in,
                              void* d_out, int out_size) {
    const float* hi = (const float*)d_in[0];
    const float* hj = (const float*)d_in[1];
    float* out = (float*)d_out;

    prep_kernel<<<2048, 256>>>(hi, hj);
    cudaFuncSetAttribute(ntxent_mma_kernel,
                         cudaFuncAttributeMaxDynamicSharedMemorySize, SMEM_BYTES);
    ntxent_mma_kernel<<<64 * NCH, 256, SMEM_BYTES>>>();
    combine_kernel<<<(BATCHSZ * 32) / 256, 256>>>(hi, hj);
    reduce_kernel<<<1, 256>>>(out);
}

// round 16
// speedup vs baseline: 1.1598x; 1.0664x over previous
#include <cuda_runtime.h>
#include <math_constants.h>
#include <cstdint>

// ---------------- problem constants ----------------
#define BATCHSZ 4096
#define DIM     256
#define NROWS   8192
#define NCH     16              // column chunks (512 cols each)
#define TPC     4               // 128-col tiles per item (512 / 128)
#define NPAIR   16              // chunk pairs per item (32 chunks / 2)
// prescale = sqrt(2 * log2(e)): product of two prescaled values = sim * 2 * log2e
#define PRESCALE 1.6986436f
#define LN2F     0.69314718055994531f

// ---------------- device scratch (no allocs allowed) ----------------
__device__ uint32_t g_afrag[64 * 16384];        // [rt][t16][ks][lane][4reg] 4MB
__device__ uint32_t g_bfrag[64 * 8 * 2048];     // [tile128][kc][nt][ks][lane][2reg] 4MB
__device__ float g_pm[NCH][NROWS];
__device__ float g_ps[NCH][NROWS];
__device__ float g_psum[512];
__device__ unsigned int g_count;                // zero-init; reset by last block

// ---------------- smem layout (u32 words) ----------------
#define A_U32    16384                  // A tile fragments (64KB)
#define B_OFF    16384                  // 4 chunk buffers x 2048 u32 (two 16KB halves)
#define B_BUF    2048
#define RED_OFF  (B_OFF + 4 * B_BUF)    // 24576: [4 wn][128 rows][m,s] floats
#define SMEM_U32 (RED_OFF + 1024)       // 25600
#define SMEM_BYTES (SMEM_U32 * 4)       // 102400

// ---------------- helpers ----------------
static __device__ __forceinline__ uint32_t f2bf2(float lo, float hi) {
    uint32_t r;   // d = {hi, lo}
    asm("cvt.rn.bf16x2.f32 %0, %1, %2;" : "=r"(r) : "f"(hi), "f"(lo));
    return r;
}
static __device__ __forceinline__ float ex2f(float x) {
    float y;
    asm("ex2.approx.ftz.f32 %0, %1;" : "=f"(y) : "f"(x));
    return y;
}
static __device__ __forceinline__ uint32_t smem_u32(const void* p) {
    uint32_t a;
    asm("{ .reg .u64 t; cvta.to.shared.u64 t, %1; cvt.u32.u64 %0, t; }" : "=r"(a) : "l"(p));
    return a;
}
static __device__ __forceinline__ void mma_bf16(float c[4],
        uint32_t a0, uint32_t a1, uint32_t a2, uint32_t a3,
        uint32_t b0, uint32_t b1) {
    asm volatile(
        "mma.sync.aligned.m16n8k16.row.col.f32.bf16.bf16.f32 "
        "{%0,%1,%2,%3}, {%4,%5,%6,%7}, {%8,%9}, {%0,%1,%2,%3};"
        : "+f"(c[0]), "+f"(c[1]), "+f"(c[2]), "+f"(c[3])
        : "r"(a0), "r"(a1), "r"(a2), "r"(a3), "r"(b0), "r"(b1));
}
#define CP_ASYNC16(dst, src) \
    asm volatile("cp.async.cg.shared.global [%0], [%1], 16;" :: "r"(dst), "l"(src))
#define CP_COMMIT() asm volatile("cp.async.commit_group;" ::: "memory")
#define CP_WAIT(n)  asm volatile("cp.async.wait_group %0;" :: "n"(n) : "memory")

static __device__ __forceinline__ const float* srow(const float* hi, const float* hj, int r) {
    return (r < BATCHSZ) ? (hi + (size_t)r * DIM) : (hj + (size_t)(r - BATCHSZ) * DIM);
}

// ==========================================================================
// Pre-pass: convert inputs to pre-scaled bf16 fragment-major layouts.
// Blocks [0,1024): g_afrag. Blocks [1024,2048): g_bfrag. 4 u32 per thread.
// ==========================================================================
__global__ void prep_kernel(const float* __restrict__ hi, const float* __restrict__ hj) {
    const int tid = threadIdx.x;
    if (blockIdx.x < 1024) {
        // afrag: ai = rt<<14 | t16<<11 | ks<<7 | lane<<2 | reg
        const int ai = blockIdx.x * 1024 + tid * 4;
        const int rt = ai >> 14, rem = ai & 16383;
        const int t16 = rem >> 11, ks = (rem >> 7) & 15, l = (rem >> 2) & 31;
        const int g = l >> 2, tq = l & 3;
        const int row0 = rt * 128 + t16 * 16 + g;
        const int kb = ks * 16 + tq * 2;
#pragma unroll
        for (int reg = 0; reg < 4; reg++) {
            const int row = row0 + (reg & 1) * 8;
            const int k = kb + (reg >> 1) * 8;
            const float2 v = *(const float2*)(srow(hi, hj, row) + k);
            g_afrag[ai + reg] = f2bf2(v.x * PRESCALE, v.y * PRESCALE);
        }
    } else {
        // bfrag: bi = tile128<<14 | kc<<11 | nt<<7 | ks<<6 | lane<<1 | reg
        const int b0 = (blockIdx.x - 1024) * 1024 + tid * 4;
#pragma unroll
        for (int j = 0; j < 4; j++) {
            const int bi = b0 + j;
            const int ct = bi >> 14, rem = bi & 16383;
            const int kc = rem >> 11, nt = (rem >> 7) & 15;
            const int ks = (rem >> 6) & 1, l = (rem >> 1) & 31, reg = bi & 1;
            const int col = ct * 128 + nt * 8 + (l >> 2);
            const int k = kc * 32 + ks * 16 + (l & 3) * 2 + reg * 8;
            const float2 v = *(const float2*)(srow(hi, hj, col) + k);
            g_bfrag[bi] = f2bf2(v.x * PRESCALE, v.y * PRESCALE);
        }
    }
}

// ==========================================================================
// Fused bf16 mma.sync GEMM + online logsumexp (base-2).
// Work item (CTA) = (row tile rt: 128 rows, A resident) x (512-col chunk ct).
// Pair-granular cp.async pipeline: each group copies a contiguous 16KB pair
// of K-chunks into one 2-buffer half; prefetch one pair ahead; ONE wait +
// ONE __syncthreads per pair (16 per item). Halves alternate, so the
// prefetch never writes the half being read; the sync orders half reuse.
// ==========================================================================
__global__ __launch_bounds__(256, 2)
void ntxent_mma_kernel() {
    extern __shared__ float smf[];
    uint32_t* smu = (uint32_t*)smf;
    const uint32_t sbase = smem_u32(smf);
    const int tid = threadIdx.x;
    const int w = tid >> 5, lane = tid & 31;
    const int g = lane >> 2, tq = lane & 3;
    const int wm = w >> 2, wn = w & 3;          // warp grid 2 x 4

    const int rt = blockIdx.x & 63;
    const int ct = blockIdx.x >> 6;             // 512-col chunk 0..15
    const int r0 = rt * 128;
    // Diagonal 128-col tile lives in this item iff ct == rt>>2; local index rt&3.
    const int tdiag = (ct == (rt >> 2)) ? (rt & 3) : -1;

    const uint32_t* asrc = g_afrag + (size_t)rt * 16384;
    const uint32_t* bbase = g_bfrag + (size_t)ct * 32 * 2048;

    // -------- prologue: cp.async A tile (group), pair 0 (group) --------
#pragma unroll
    for (int i = 0; i < 16; i++) {
        const int ga = i * 256 + tid;
        CP_ASYNC16(sbase + ga * 16, asrc + ga * 4);
    }
    CP_COMMIT();
#pragma unroll
    for (int i = 0; i < 4; i++) {
        const int gi = i * 256 + tid;
        CP_ASYNC16(sbase + (B_OFF + gi * 4) * 4, bbase + gi * 4);
    }
    CP_COMMIT();

    float acc[4][4][4];
#pragma unroll
    for (int mf = 0; mf < 4; mf++)
#pragma unroll
        for (int nf = 0; nf < 4; nf++)
#pragma unroll
            for (int c = 0; c < 4; c++) acc[mf][nf][c] = 0.f;

    // Running per-segment (m, s): seg s = mf*2+hh covers row wm*64+mf*16+g+hh*8.
    float rM[8], rS[8];
#pragma unroll
    for (int s = 0; s < 8; s++) { rM[s] = -CUDART_INF_F; rS[s] = 0.f; }

    for (int p = 0; p < NPAIR; p++) {
        // Drain all copies: pair p (the only possibly-outstanding group) lands.
        CP_WAIT(0);
        __syncthreads();                // all warps done with the reused half

        if (p + 1 < NPAIR) {            // prefetch pair p+1 into the other half
            const uint32_t boffu = (uint32_t)(B_OFF + (((p + 1) & 1) * 2) * B_BUF);
            const uint32_t* src = bbase + (size_t)(p + 1) * 4096;
#pragma unroll
            for (int i = 0; i < 4; i++) {
                const int gi = i * 256 + tid;
                CP_ASYNC16(sbase + (boffu + gi * 4) * 4, src + gi * 4);
            }
            CP_COMMIT();
        }

        // -------- MMA: 2 chunks x 2 k16-steps on pair p --------
        const uint32_t rdoff = (uint32_t)(B_OFF + ((p & 1) * 2) * B_BUF);
#pragma unroll
        for (int kc2 = 0; kc2 < 2; kc2++) {
            const int kc = (2 * p + kc2) & 7;    // chunk index within tile (k pos)
            const uint32_t* Bu = smu + rdoff + kc2 * B_BUF;
#pragma unroll
            for (int ksl = 0; ksl < 2; ksl++) {
                uint2 bfr[4];
#pragma unroll
                for (int nf = 0; nf < 4; nf++)
                    bfr[nf] = *(const uint2*)(Bu + ((wn * 4 + nf) * 2 + ksl) * 64
                                              + lane * 2);
#pragma unroll
                for (int mf = 0; mf < 4; mf++) {
                    const uint4 af = *(const uint4*)(smu
                        + ((wm * 4 + mf) * 16 + (kc * 2 + ksl)) * 128 + lane * 4);
#pragma unroll
                    for (int nf = 0; nf < 4; nf++)
                        mma_bf16(acc[mf][nf], af.x, af.y, af.z, af.w,
                                 bfr[nf].x, bfr[nf].y);
                }
            }
        }

        // -------- epilogue every 4 pairs (one 128-col tile done), base-2 ------
        if ((p & 3) == 3) {
            const int t = p >> 2;
            const bool hd = (t == tdiag);
            const int cloc = wn * 32 + tq * 2;           // tile-local col base
            const int rloc = wm * 64 + g;                // tile-local row base
#pragma unroll
            for (int mf = 0; mf < 4; mf++)
#pragma unroll
                for (int hh = 0; hh < 2; hh++) {
                    const int s = mf * 2 + hh;
                    float m = -CUDART_INF_F;
                    if (hd) {
                        const int gr = rloc + mf * 16 + hh * 8;  // tile-local row
#pragma unroll
                        for (int nf = 0; nf < 4; nf++)
#pragma unroll
                            for (int c = 0; c < 2; c++) {
                                float v = acc[mf][nf][hh * 2 + c];
                                if (gr == cloc + nf * 8 + c) v = -CUDART_INF_F;
                                acc[mf][nf][hh * 2 + c] = v;
                                m = fmaxf(m, v);
                            }
                    } else {
#pragma unroll
                        for (int nf = 0; nf < 4; nf++)
#pragma unroll
                            for (int c = 0; c < 2; c++)
                                m = fmaxf(m, acc[mf][nf][hh * 2 + c]);
                    }
                    m = fmaxf(m, __shfl_xor_sync(0xffffffffu, m, 1));
                    m = fmaxf(m, __shfl_xor_sync(0xffffffffu, m, 2));
                    float sv = 0.f;
#pragma unroll
                    for (int nf = 0; nf < 4; nf++)
#pragma unroll
                        for (int c = 0; c < 2; c++)
                            sv += ex2f(acc[mf][nf][hh * 2 + c] - m);
                    sv += __shfl_xor_sync(0xffffffffu, sv, 1);
                    sv += __shfl_xor_sync(0xffffffffu, sv, 2);
                    const float nm = fmaxf(rM[s], m);
                    rS[s] = rS[s] * ex2f(rM[s] - nm) + sv * ex2f(m - nm);
                    rM[s] = nm;
#pragma unroll
                    for (int nf = 0; nf < 4; nf++)
#pragma unroll
                        for (int c = 0; c < 2; c++)
                            acc[mf][nf][hh * 2 + c] = 0.f;
                }
        }
    }

    // -------- final cross-warp merge (once per item) --------
    {
        float* red = smf + RED_OFF;              // [wn][128 rows][m,s]
        if (tq == 0) {
#pragma unroll
            for (int s = 0; s < 8; s++) {
                const int row = wm * 64 + (s >> 1) * 16 + g + (s & 1) * 8;
                red[(wn * 128 + row) * 2 + 0] = rM[s];
                red[(wn * 128 + row) * 2 + 1] = rS[s];
            }
        }
        __syncthreads();
        if (tid < 128) {                         // thread tid owns row r0+tid
            float M = red[tid * 2];
#pragma unroll
            for (int q = 1; q < 4; q++) M = fmaxf(M, red[(q * 128 + tid) * 2]);
            float S = 0.f;
#pragma unroll
            for (int q = 0; q < 4; q++)
                S += red[(q * 128 + tid) * 2 + 1] * ex2f(red[(q * 128 + tid) * 2] - M);
            g_pm[ct][r0 + tid] = M;              // base-2 max of sim*2*log2e
            g_ps[ct][r0 + tid] = S;              // base-2 sumexp
        }
    }
}

// ==========================================================================
// Fused combine + reduce: 512 blocks x 8 pairs. Each block merges 16 chunk
// partials per row, computes exact fp32 pos, block-reduces its 16 losses
// (fixed order), writes g_psum[bid]; the last-arriving block tree-reduces
// the 512 partials -> mean, and resets the counter (replay-safe).
// ==========================================================================
__global__ void combine_reduce_kernel(const float* __restrict__ hi,
                                      const float* __restrict__ hj,
                                      float* __restrict__ out) {
    __shared__ float sl[16];
    __shared__ float sred[256];
    __shared__ bool is_last;
    const int tid = threadIdx.x;
    const int w = tid >> 5, lane = tid & 31;
    const int gwarp = blockIdx.x * 8 + w;        // pair index 0..4095

    const float* a = hi + (size_t)gwarp * DIM;
    const float* b = hj + (size_t)gwarp * DIM;
    const int k = lane * 8;
    float4 a0 = *(const float4*)(a + k);
    float4 a1 = *(const float4*)(a + k + 4);
    float4 b0 = *(const float4*)(b + k);
    float4 b1 = *(const float4*)(b + k + 4);
    float d = a0.x * b0.x + a0.y * b0.y + a0.z * b0.z + a0.w * b0.w
            + a1.x * b1.x + a1.y * b1.y + a1.z * b1.z + a1.w * b1.w;
#pragma unroll
    for (int off = 16; off > 0; off >>= 1)
        d += __shfl_xor_sync(0xffffffffu, d, off);
    const float pos = d * 2.0f;                  // exact fp32 sim / temp

    if (lane < 2) {
        const int r = gwarp + lane * BATCHSZ;
        float M = g_pm[0][r];
#pragma unroll
        for (int c = 1; c < NCH; c++) M = fmaxf(M, g_pm[c][r]);
        float S = 0.f;
#pragma unroll
        for (int c = 0; c < NCH; c++) S += g_ps[c][r] * ex2f(g_pm[c][r] - M);
        sl[w * 2 + lane] = LN2F * (M + __log2f(S)) - pos;   // per-row loss
    }
    __syncthreads();

    if (tid == 0) {
        float s = 0.f;
#pragma unroll
        for (int i = 0; i < 16; i++) s += sl[i];  // fixed order: deterministic
        g_psum[blockIdx.x] = s;
        __threadfence();
        const unsigned int tkt = atomicAdd(&g_count, 1u);
        is_last = (tkt == 511u);
    }
    __syncthreads();

    if (is_last) {
        __threadfence();                          // observe all g_psum writes
        float s = g_psum[tid] + g_psum[tid + 256];
        sred[tid] = s;
        __syncthreads();
        for (int stride = 128; stride > 0; stride >>= 1) {
            if (tid < stride) sred[tid] += sred[tid + stride];
            __syncthreads();
        }
        if (tid == 0) {
            out[0] = sred[0] * (1.0f / NROWS);
            g_count = 0;                          // reset for next graph replay
        }
    }
}

extern "C" void kernel_launch(void* const* d_in, const int* in_sizes, int n_in,
                              void* d_out, int out_size) {
    const float* hi = (const float*)d_in[0];
    const float* hj = (const float*)d_in[1];
    float* out = (float*)d_out;

    prep_kernel<<<2048, 256>>>(hi, hj);
    cudaFuncSetAttribute(ntxent_mma_kernel,
                         cudaFuncAttributeMaxDynamicSharedMemorySize, SMEM_BYTES);
    ntxent_mma_kernel<<<64 * NCH, 256, SMEM_BYTES>>>();
    combine_reduce_kernel<<<512, 256>>>(hi, hj, out);
}